// round 16
// baseline (speedup 1.0000x reference)
#include <cuda_runtime.h>
#include <cuda_bf16.h>
#include <math.h>
#include <cstdint>

// Problem dims
#define BB   16
#define N1   2048
#define N2   2048
#define HH   768
#define LAT  128
#define MID  256
#define RTOT (BB * N1)

typedef __nv_bfloat16  bf16;
typedef __nv_bfloat162 bf162;

// ---------------------------------------------------------------------------
// Scratch (device globals)
// ---------------------------------------------------------------------------
__device__ bf16 g_mid2[2 * RTOT * MID];   // [main | feat] hidden; also decode hidden
__device__ bf16 g_mf  [2 * RTOT * LAT];   // [m | f]
__device__ bf16 g_q   [RTOT * LAT];
__device__ bf16 g_kv  [RTOT * 256];       // interleaved: cols 0-127 K, 128-255 V
__device__ bf16 g_attn[RTOT * LAT];
__device__ bf16 g_wb_e1[MID * HH];
__device__ bf16 g_wb_e2[LAT * MID];
__device__ bf16 g_wb_q [LAT * LAT];
__device__ bf16 g_wb_kv[256 * LAT];       // rows 0-127 Wk^T, 128-255 Wv^T
__device__ bf16 g_wb_d1[MID * LAT];
__device__ bf16 g_wb_d2[HH * MID];
__device__ float g_bias_kv[256];

// ---------------------------------------------------------------------------
// Helpers
// ---------------------------------------------------------------------------
__device__ __forceinline__ void mma16(float c[4], const uint32_t a[4], const uint32_t b[2]) {
    asm volatile(
        "mma.sync.aligned.m16n8k16.row.col.f32.bf16.bf16.f32 "
        "{%0,%1,%2,%3}, {%4,%5,%6,%7}, {%8,%9}, {%0,%1,%2,%3};"
        : "+f"(c[0]), "+f"(c[1]), "+f"(c[2]), "+f"(c[3])
        : "r"(a[0]), "r"(a[1]), "r"(a[2]), "r"(a[3]), "r"(b[0]), "r"(b[1]));
}
__device__ __forceinline__ uint32_t smem_u32(const void* p) {
    uint32_t a;
    asm("{ .reg .u64 t; cvta.to.shared.u64 t, %1; cvt.u32.u64 %0, t; }"
        : "=r"(a) : "l"(p));
    return a;
}
__device__ __forceinline__ void ldsm4(uint32_t& r0, uint32_t& r1, uint32_t& r2,
                                      uint32_t& r3, uint32_t addr) {
    asm volatile("ldmatrix.sync.aligned.m8n8.x4.shared.b16 {%0,%1,%2,%3}, [%4];"
                 : "=r"(r0), "=r"(r1), "=r"(r2), "=r"(r3) : "r"(addr));
}
__device__ __forceinline__ void ldsm4t(uint32_t& r0, uint32_t& r1, uint32_t& r2,
                                       uint32_t& r3, uint32_t addr) {
    asm volatile("ldmatrix.sync.aligned.m8n8.x4.trans.shared.b16 {%0,%1,%2,%3}, [%4];"
                 : "=r"(r0), "=r"(r1), "=r"(r2), "=r"(r3) : "r"(addr));
}
__device__ __forceinline__ void cpa16(uint32_t dst, const void* src) {
    asm volatile("cp.async.cg.shared.global [%0], [%1], 16;" :: "r"(dst), "l"(src));
}
#define CP_COMMIT() asm volatile("cp.async.commit_group;")
#define CP_WAIT1()  asm volatile("cp.async.wait_group 1;")
__device__ __forceinline__ uint32_t pkbf(float a, float b) {
    bf162 h = __floats2bfloat162_rn(a, b);
    return *(uint32_t*)&h;
}

// ---------------------------------------------------------------------------
// Fused weight transpose -> bf16 [N,K]; K/V packed into wb_kv; bias_kv packed.
// ---------------------------------------------------------------------------
__global__ void transpose_all(
    const float* __restrict__ We1, bf16* __restrict__ wb_e1,
    const float* __restrict__ We2, bf16* __restrict__ wb_e2,
    const float* __restrict__ Wq,  bf16* __restrict__ wb_q,
    const float* __restrict__ Wk,
    const float* __restrict__ Wv,  bf16* __restrict__ wb_kv,
    const float* __restrict__ Wd1, bf16* __restrict__ wb_d1,
    const float* __restrict__ Wd2, bf16* __restrict__ wb_d2,
    const float* __restrict__ bk, const float* __restrict__ bv,
    float* __restrict__ bias_kv)
{
    __shared__ float t[32][33];
    int idx = blockIdx.x;
    int x = threadIdx.x, y = threadIdx.y;   // 32 x 8
    if (idx == 496) {                       // bias pack block
        int flat = y * 32 + x;
        bias_kv[flat] = (flat < 128) ? bk[flat] : bv[flat - 128];
        return;
    }
    const float* in; bf16* out; int K, N, l;
    if (idx < 192)      { in = We1; out = wb_e1; K = HH;  N = MID; l = idx; }
    else if (idx < 224) { in = We2; out = wb_e2; K = MID; N = LAT; l = idx - 192; }
    else if (idx < 240) { in = Wq;  out = wb_q;  K = LAT; N = LAT; l = idx - 224; }
    else if (idx < 256) { in = Wk;  out = wb_kv; K = LAT; N = LAT; l = idx - 240; }
    else if (idx < 272) { in = Wv;  out = wb_kv + 128 * LAT; K = LAT; N = LAT; l = idx - 256; }
    else if (idx < 304) { in = Wd1; out = wb_d1; K = LAT; N = MID; l = idx - 272; }
    else                { in = Wd2; out = wb_d2; K = MID; N = HH;  l = idx - 304; }
    int tx = N >> 5;
    int nx = (l % tx) * 32, kx = (l / tx) * 32;
#pragma unroll
    for (int i = 0; i < 32; i += 8)
        t[y + i][x] = in[(long)(kx + y + i) * N + nx + x];
    __syncthreads();
#pragma unroll
    for (int i = 0; i < 32; i += 8)
        out[(long)(nx + y + i) * K + kx + x] = __float2bfloat16(t[x][y + i]);
}

// ---------------------------------------------------------------------------
// bf16 mma GEMM: C = act(A_bf16 @ Wt_bf16^T + bias)
// CTA 128xBN, BK=64 bf16, 3-stage cp.async, m16n8k16.
// ---------------------------------------------------------------------------
#define BPAD 72

template <int ACT, int BN, int OUT32>
__global__ __launch_bounds__(256) void gemm_bf16(
    const bf16* __restrict__ A, const bf16* __restrict__ Wt,
    const float* __restrict__ bias, void* __restrict__ Cv,
    int M, int N, int K)
{
    extern __shared__ char smraw[];
    bf16* smb = (bf16*)smraw;
    constexpr int STG_A = 128 * BPAD;
    constexpr int STG_B = BN * BPAD;
    constexpr int STG   = STG_A + STG_B;
    constexpr int NT    = BN / 32;

    const int tid = threadIdx.x;
    const int wid = tid >> 5, lane = tid & 31;
    const int g = lane >> 2, t4 = lane & 3;
    const int wm = (wid & 1) * 64;
    const int wn = (wid >> 1) * (BN / 4);
    const int m0 = blockIdx.y * 128, n0 = blockIdx.x * BN;

    float c[4][NT][4];
#pragma unroll
    for (int mt = 0; mt < 4; mt++)
#pragma unroll
        for (int nt = 0; nt < NT; nt++)
#pragma unroll
            for (int i = 0; i < 4; i++) c[mt][nt][i] = 0.f;

    const int nk = K >> 6;

    auto load_stage = [&](int kt, int s) {
        bf16* base = smb + s * STG;
#pragma unroll
        for (int i = 0; i < 4; i++) {
            int idx = tid + i * 256;
            int r = idx >> 3, c8 = idx & 7;
            cpa16(smem_u32(base + r * BPAD + c8 * 8),
                  A + (long)(m0 + r) * K + kt * 64 + c8 * 8);
        }
#pragma unroll
        for (int i = 0; i < BN / 32; i++) {
            int idx = tid + i * 256;
            int r = idx >> 3, c8 = idx & 7;
            cpa16(smem_u32(base + STG_A + r * BPAD + c8 * 8),
                  Wt + (long)(n0 + r) * K + kt * 64 + c8 * 8);
        }
    };

    const int mat = lane >> 3, rowin = lane & 7;
    const uint32_t a0 = smem_u32(smb)
        + (uint32_t)((wm + (mat & 1) * 8 + rowin) * BPAD + (mat >> 1) * 8) * 2;
    const uint32_t b0 = smem_u32(smb) + (uint32_t)STG_A * 2
        + (uint32_t)((wn + (mat >> 1) * 8 + rowin) * BPAD + (mat & 1) * 8) * 2;

    load_stage(0, 0); CP_COMMIT();
    load_stage(1, 1); CP_COMMIT();

    for (int kt = 0; kt < nk; kt++) {
        CP_WAIT1();
        __syncthreads();
        if (kt + 2 < nk) load_stage(kt + 2, (kt + 2) % 3);
        CP_COMMIT();

        int s = kt % 3;
        uint32_t ab = a0 + (uint32_t)(s * STG) * 2;
        uint32_t bb = b0 + (uint32_t)(s * STG) * 2;
#pragma unroll
        for (int ks = 0; ks < 4; ks++) {
            uint32_t af[4][4], bfr[NT][2];
#pragma unroll
            for (int mt = 0; mt < 4; mt++)
                ldsm4(af[mt][0], af[mt][1], af[mt][2], af[mt][3],
                      ab + mt * (16 * BPAD * 2) + ks * 32);
#pragma unroll
            for (int p = 0; p < NT / 2; p++)
                ldsm4(bfr[2 * p][0], bfr[2 * p][1], bfr[2 * p + 1][0], bfr[2 * p + 1][1],
                      bb + p * (16 * BPAD * 2) + ks * 32);
#pragma unroll
            for (int mt = 0; mt < 4; mt++)
#pragma unroll
                for (int nt = 0; nt < NT; nt++)
                    mma16(c[mt][nt], af[mt], bfr[nt]);
        }
    }

#pragma unroll
    for (int mt = 0; mt < 4; mt++) {
        int r0 = m0 + wm + mt * 16 + g;
#pragma unroll
        for (int nt = 0; nt < NT; nt++) {
            int col = n0 + wn + nt * 8 + 2 * t4;
            float2 bv = *(const float2*)(bias + col);
            float x0 = c[mt][nt][0] + bv.x;
            float x1 = c[mt][nt][1] + bv.y;
            float x2 = c[mt][nt][2] + bv.x;
            float x3 = c[mt][nt][3] + bv.y;
            if (ACT == 1) {
                x0 = fmaxf(x0, 0.f); x1 = fmaxf(x1, 0.f);
                x2 = fmaxf(x2, 0.f); x3 = fmaxf(x3, 0.f);
            }
            if (ACT == 2) {
                x0 = 1.f / (1.f + __expf(-x0)); x1 = 1.f / (1.f + __expf(-x1));
                x2 = 1.f / (1.f + __expf(-x2)); x3 = 1.f / (1.f + __expf(-x3));
            }
            if (OUT32) {
                float* C = (float*)Cv;
                *(float2*)(C + (long)r0 * N + col)       = make_float2(x0, x1);
                *(float2*)(C + (long)(r0 + 8) * N + col) = make_float2(x2, x3);
            } else {
                bf16* C = (bf16*)Cv;
                *(bf162*)(C + (long)r0 * N + col)       = __floats2bfloat162_rn(x0, x1);
                *(bf162*)(C + (long)(r0 + 8) * N + col) = __floats2bfloat162_rn(x2, x3);
            }
        }
    }
}

// ---------------------------------------------------------------------------
// Stage-1 GEMM, fused fp32->bf16 on A, BOTH inputs in one launch.
// blockIdx.y < HB: rows of A0 (main); else rows of A1 (feat).
// ---------------------------------------------------------------------------
__global__ __launch_bounds__(256) void gemm_e1f(
    const float* __restrict__ A0, const float* __restrict__ A1,
    const bf16* __restrict__ Wt,
    const float* __restrict__ bias, bf16* __restrict__ C,
    int Mhalf, int N, int K)
{
    extern __shared__ char smraw[];
    bf16* smb = (bf16*)smraw;
    constexpr int BN = 256;
    constexpr int STG_A = 128 * BPAD;
    constexpr int STG_B = BN * BPAD;
    constexpr int NT = 8;
    bf16* Asm = smb;                 // 2 stages
    bf16* Bsm = smb + 2 * STG_A;     // 3 stages

    const int tid = threadIdx.x;
    const int wid = tid >> 5, lane = tid & 31;
    const int g = lane >> 2, t4 = lane & 3;
    const int wm = (wid & 1) * 64;
    const int wn = (wid >> 1) * 64;

    const int hb = Mhalf / 128;
    const int half = blockIdx.y >= hb;
    const float* A = half ? A1 : A0;
    const int m0 = (blockIdx.y - half * hb) * 128;   // row in A
    const long crow0 = (long)blockIdx.y * 128;       // row in C (contiguous halves)
    const int n0 = blockIdx.x * BN;

    float c[4][NT][4];
#pragma unroll
    for (int mt = 0; mt < 4; mt++)
#pragma unroll
        for (int nt = 0; nt < NT; nt++)
#pragma unroll
            for (int i = 0; i < 4; i++) c[mt][nt][i] = 0.f;

    const int nk = K >> 6;          // 12 for K=768

    const int arow = tid >> 1, ahalf = (tid & 1) * 32;
    float4 ar[8];
    auto ldA = [&](int kt) {
        const float* Ar = A + (long)(m0 + arow) * K + kt * 64 + ahalf;
#pragma unroll
        for (int i = 0; i < 8; i++) ar[i] = *(const float4*)(Ar + i * 4);
    };
    auto stA = [&](int buf) {
        bf16* d = Asm + buf * STG_A + arow * BPAD + ahalf;
#pragma unroll
        for (int i = 0; i < 4; i++) {
            uint4 u;
            u.x = pkbf(ar[2 * i].x,     ar[2 * i].y);
            u.y = pkbf(ar[2 * i].z,     ar[2 * i].w);
            u.z = pkbf(ar[2 * i + 1].x, ar[2 * i + 1].y);
            u.w = pkbf(ar[2 * i + 1].z, ar[2 * i + 1].w);
            *(uint4*)(d + i * 8) = u;
        }
    };
    auto loadB = [&](int kt, int s) {
        bf16* base = Bsm + s * STG_B;
#pragma unroll
        for (int i = 0; i < 8; i++) {
            int idx = tid + i * 256;
            int r = idx >> 3, c8 = idx & 7;
            cpa16(smem_u32(base + r * BPAD + c8 * 8),
                  Wt + (long)(n0 + r) * K + kt * 64 + c8 * 8);
        }
    };

    const int mat = lane >> 3, rowin = lane & 7;
    const uint32_t a0 = smem_u32(Asm)
        + (uint32_t)((wm + (mat & 1) * 8 + rowin) * BPAD + (mat >> 1) * 8) * 2;
    const uint32_t b0 = smem_u32(Bsm)
        + (uint32_t)((wn + (mat >> 1) * 8 + rowin) * BPAD + (mat & 1) * 8) * 2;

    ldA(0);
    loadB(0, 0); CP_COMMIT();
    loadB(1, 1); CP_COMMIT();
    stA(0);

    for (int kt = 0; kt < nk; kt++) {
        if (kt + 1 < nk) ldA(kt + 1);
        CP_WAIT1();
        __syncthreads();
        if (kt + 2 < nk) loadB(kt + 2, (kt + 2) % 3);
        CP_COMMIT();

        uint32_t ab = a0 + (uint32_t)((kt & 1) * STG_A) * 2;
        uint32_t bb = b0 + (uint32_t)((kt % 3) * STG_B) * 2;
#pragma unroll
        for (int ks = 0; ks < 4; ks++) {
            uint32_t af[4][4], bfr[NT][2];
#pragma unroll
            for (int mt = 0; mt < 4; mt++)
                ldsm4(af[mt][0], af[mt][1], af[mt][2], af[mt][3],
                      ab + mt * (16 * BPAD * 2) + ks * 32);
#pragma unroll
            for (int p = 0; p < NT / 2; p++)
                ldsm4(bfr[2 * p][0], bfr[2 * p][1], bfr[2 * p + 1][0], bfr[2 * p + 1][1],
                      bb + p * (16 * BPAD * 2) + ks * 32);
#pragma unroll
            for (int mt = 0; mt < 4; mt++)
#pragma unroll
                for (int nt = 0; nt < NT; nt++)
                    mma16(c[mt][nt], af[mt], bfr[nt]);
        }
        if (kt + 1 < nk) stA((kt + 1) & 1);
    }

#pragma unroll
    for (int mt = 0; mt < 4; mt++) {
        long r0 = crow0 + wm + mt * 16 + g;
#pragma unroll
        for (int nt = 0; nt < NT; nt++) {
            int col = n0 + wn + nt * 8 + 2 * t4;
            float2 bv = *(const float2*)(bias + col);
            float x0 = fmaxf(c[mt][nt][0] + bv.x, 0.f);
            float x1 = fmaxf(c[mt][nt][1] + bv.y, 0.f);
            float x2 = fmaxf(c[mt][nt][2] + bv.x, 0.f);
            float x3 = fmaxf(c[mt][nt][3] + bv.y, 0.f);
            *(bf162*)(C + r0 * N + col)       = __floats2bfloat162_rn(x0, x1);
            *(bf162*)(C + (r0 + 8) * N + col) = __floats2bfloat162_rn(x2, x3);
        }
    }
}

// ---------------------------------------------------------------------------
// Flash attention: BN=128 key tiles, register softmax, S->P fragment reuse,
// double-buffered cp.async K/V from packed g_kv, Q fragments preloaded.
// ---------------------------------------------------------------------------
#define FA_BM 128
#define FA_BN 128
#define FQS   136
// smem: Qs [128][FQS] + 2 x KV stage [256][FQS] (K rows 0-127, V rows 128-255)
#define FA_SMEM_BYTES ((128 * FQS + 2 * 256 * FQS) * 2)

__global__ __launch_bounds__(256, 1) void flash_attn_bf16(
    const bf16* __restrict__ Q, const bf16* __restrict__ KV,
    bf16* __restrict__ O)
{
    extern __shared__ char smraw[];
    bf16* Qs  = (bf16*)smraw;                // [128][FQS]
    bf16* KVs = Qs + 128 * FQS;              // [2][256][FQS]

    const int tid = threadIdx.x;
    const int b   = blockIdx.y;
    const int m0  = blockIdx.x * FA_BM;

    const bf16* Qb = Q + ((long)b * N1 + m0) * LAT;
    const bf16* Kb = KV + (long)b * N2 * 256;       // cols 0-127 K
    const bf16* Vb = Kb + 128;                      // cols 128-255 V

    const int wid = tid >> 5, lane = tid & 31;
    const int g = lane >> 2, t4 = lane & 3;
    const int mat = lane >> 3, rowin = lane & 7;
    const int qr0 = wid * 16;

    // Load Q tile
#pragma unroll
    for (int i = 0; i < 8; i++) {
        int idx = tid + i * 256;
        int r = idx >> 4, c8 = idx & 15;
        *(uint4*)(Qs + r * FQS + c8 * 8) = *(const uint4*)(Qb + r * LAT + c8 * 8);
    }

    auto loadKV = [&](int t, int s) {
        bf16* base = KVs + s * 256 * FQS;
#pragma unroll
        for (int i = 0; i < 8; i++) {
            int idx = tid + i * 256;
            int r = idx >> 4, c8 = idx & 15;
            cpa16(smem_u32(base + r * FQS + c8 * 8),
                  Kb + (long)(t * FA_BN + r) * 256 + c8 * 8);
        }
#pragma unroll
        for (int i = 0; i < 8; i++) {
            int idx = tid + i * 256;
            int r = idx >> 4, c8 = idx & 15;
            cpa16(smem_u32(base + (128 + r) * FQS + c8 * 8),
                  Vb + (long)(t * FA_BN + r) * 256 + c8 * 8);
        }
    };

    const uint32_t aq = smem_u32(Qs)
        + (uint32_t)((qr0 + (mat & 1) * 8 + rowin) * FQS + (mat >> 1) * 8) * 2;
    const uint32_t bk0 = smem_u32(KVs)
        + (uint32_t)(((mat >> 1) * 8 + rowin) * FQS + (mat & 1) * 8) * 2;
    const uint32_t bv0 = smem_u32(KVs) + (uint32_t)(128 * FQS) * 2
        + (uint32_t)(((mat & 1) * 8 + rowin) * FQS + (mat >> 1) * 8) * 2;

    float m0r = -INFINITY, m1r = -INFINITY, l0 = 0.f, l1 = 0.f;
    float oc[16][4];
#pragma unroll
    for (int nt = 0; nt < 16; nt++)
#pragma unroll
        for (int i = 0; i < 4; i++) oc[nt][i] = 0.f;

    loadKV(0, 0); CP_COMMIT();
    loadKV(1, 1); CP_COMMIT();
    __syncthreads();   // Q visible

    // Preload all Q fragments (K=128 -> 8 ksteps)
    uint32_t qf[8][4];
#pragma unroll
    for (int ks = 0; ks < 8; ks++)
        ldsm4(qf[ks][0], qf[ks][1], qf[ks][2], qf[ks][3], aq + ks * 32);

    const int NTILES = N2 / FA_BN;   // 16
    for (int t = 0; t < NTILES; t++) {
        CP_WAIT1();
        __syncthreads();

        int s = t & 1;
        uint32_t bk = bk0 + (uint32_t)(s * 256 * FQS) * 2;
        uint32_t bv = bv0 + (uint32_t)(s * 256 * FQS) * 2;

        // --- S = Q @ K^T (8 ksteps over d; 128 keys = 16 n-tiles) ---
        float c[16][4];
#pragma unroll
        for (int nt = 0; nt < 16; nt++)
#pragma unroll
            for (int i = 0; i < 4; i++) c[nt][i] = 0.f;

#pragma unroll
        for (int ks = 0; ks < 8; ks++) {
            uint32_t bfr[16][2];
#pragma unroll
            for (int p = 0; p < 8; p++)
                ldsm4(bfr[2 * p][0], bfr[2 * p][1], bfr[2 * p + 1][0], bfr[2 * p + 1][1],
                      bk + p * (16 * FQS * 2) + ks * 32);
#pragma unroll
            for (int nt = 0; nt < 16; nt++)
                mma16(c[nt], qf[ks], bfr[nt]);
        }

        // --- Register online softmax (rows qr0+g and qr0+g+8) ---
        float mx0 = c[0][0], mx1 = c[0][2];
#pragma unroll
        for (int nt = 0; nt < 16; nt++) {
            mx0 = fmaxf(mx0, fmaxf(c[nt][0], c[nt][1]));
            mx1 = fmaxf(mx1, fmaxf(c[nt][2], c[nt][3]));
        }
        mx0 = fmaxf(mx0, __shfl_xor_sync(0xFFFFFFFFu, mx0, 1));
        mx0 = fmaxf(mx0, __shfl_xor_sync(0xFFFFFFFFu, mx0, 2));
        mx1 = fmaxf(mx1, __shfl_xor_sync(0xFFFFFFFFu, mx1, 1));
        mx1 = fmaxf(mx1, __shfl_xor_sync(0xFFFFFFFFu, mx1, 2));
        float mn0 = fmaxf(m0r, mx0), mn1 = fmaxf(m1r, mx1);
        float al0 = __expf(m0r - mn0), al1 = __expf(m1r - mn1);
        float s0 = 0.f, s1 = 0.f;
#pragma unroll
        for (int nt = 0; nt < 16; nt++) {
            float e0 = __expf(c[nt][0] - mn0);
            float e1 = __expf(c[nt][1] - mn0);
            float e2 = __expf(c[nt][2] - mn1);
            float e3 = __expf(c[nt][3] - mn1);
            c[nt][0] = e0; c[nt][1] = e1; c[nt][2] = e2; c[nt][3] = e3;
            s0 += e0 + e1; s1 += e2 + e3;
        }
        s0 += __shfl_xor_sync(0xFFFFFFFFu, s0, 1);
        s0 += __shfl_xor_sync(0xFFFFFFFFu, s0, 2);
        s1 += __shfl_xor_sync(0xFFFFFFFFu, s1, 1);
        s1 += __shfl_xor_sync(0xFFFFFFFFu, s1, 2);
        l0 = l0 * al0 + s0; l1 = l1 * al1 + s1;
        m0r = mn0; m1r = mn1;

#pragma unroll
        for (int nt = 0; nt < 16; nt++) {
            oc[nt][0] *= al0; oc[nt][1] *= al0;
            oc[nt][2] *= al1; oc[nt][3] *= al1;
        }

        // --- O += P @ V (8 ksteps over 128 keys; d = 16 n-tiles) ---
#pragma unroll
        for (int ks = 0; ks < 8; ks++) {
            uint32_t pf[4];
            pf[0] = pkbf(c[2 * ks][0],     c[2 * ks][1]);
            pf[1] = pkbf(c[2 * ks][2],     c[2 * ks][3]);
            pf[2] = pkbf(c[2 * ks + 1][0], c[2 * ks + 1][1]);
            pf[3] = pkbf(c[2 * ks + 1][2], c[2 * ks + 1][3]);
            uint32_t vf[16][2];
#pragma unroll
            for (int p = 0; p < 8; p++)
                ldsm4t(vf[2 * p][0], vf[2 * p][1], vf[2 * p + 1][0], vf[2 * p + 1][1],
                       bv + ks * (16 * FQS * 2) + p * 32);
#pragma unroll
            for (int nt = 0; nt < 16; nt++)
                mma16(oc[nt], pf, vf[nt]);
        }
        __syncthreads();
        if (t + 2 < NTILES) loadKV(t + 2, s);
        CP_COMMIT();
    }

    // --- Epilogue ---
    float inv0 = 1.f / l0, inv1 = 1.f / l1;
    long row0 = (long)b * N1 + m0 + qr0 + g;
#pragma unroll
    for (int nt = 0; nt < 16; nt++) {
        int col = nt * 8 + 2 * t4;
        *(bf162*)(O + row0 * LAT + col) =
            __floats2bfloat162_rn(oc[nt][0] * inv0, oc[nt][1] * inv0);
        *(bf162*)(O + (row0 + 8) * LAT + col) =
            __floats2bfloat162_rn(oc[nt][2] * inv1, oc[nt][3] * inv1);
    }
}

// ---------------------------------------------------------------------------
// Host launcher
// ---------------------------------------------------------------------------
extern "C" void kernel_launch(void* const* d_in, const int* in_sizes, int n_in,
                              void* d_out, int out_size)
{
    const float* mainf = (const float*)d_in[0];
    const float* feat  = (const float*)d_in[1];
    const float* We1   = (const float*)d_in[2];
    const float* be1   = (const float*)d_in[3];
    const float* We2   = (const float*)d_in[4];
    const float* be2   = (const float*)d_in[5];
    const float* Wq    = (const float*)d_in[6];
    const float* bq    = (const float*)d_in[7];
    const float* Wk    = (const float*)d_in[8];
    const float* bk    = (const float*)d_in[9];
    const float* Wv    = (const float*)d_in[10];
    const float* bv    = (const float*)d_in[11];
    const float* Wd1   = (const float*)d_in[12];
    const float* bd1   = (const float*)d_in[13];
    const float* Wd2   = (const float*)d_in[14];
    const float* bd2   = (const float*)d_in[15];
    float* out = (float*)d_out;

    bf16 *p_mid2, *p_mf, *p_q, *p_kv, *p_attn;
    bf16 *wb_e1, *wb_e2, *wb_q, *wb_kv, *wb_d1, *wb_d2;
    float* bias_kv;
    cudaGetSymbolAddress((void**)&p_mid2, g_mid2);
    cudaGetSymbolAddress((void**)&p_mf,   g_mf);
    cudaGetSymbolAddress((void**)&p_q,    g_q);
    cudaGetSymbolAddress((void**)&p_kv,   g_kv);
    cudaGetSymbolAddress((void**)&p_attn, g_attn);
    cudaGetSymbolAddress((void**)&wb_e1, g_wb_e1);
    cudaGetSymbolAddress((void**)&wb_e2, g_wb_e2);
    cudaGetSymbolAddress((void**)&wb_q,  g_wb_q);
    cudaGetSymbolAddress((void**)&wb_kv, g_wb_kv);
    cudaGetSymbolAddress((void**)&wb_d1, g_wb_d1);
    cudaGetSymbolAddress((void**)&wb_d2, g_wb_d2);
    cudaGetSymbolAddress((void**)&bias_kv, g_bias_kv);

    const int gb256_sm = 3 * (128 + 256) * BPAD * 2;              // 165888
    const int gb128_sm = 3 * (128 + 128) * BPAD * 2;              // 110592
    const int e1f_sm   = (2 * 128 + 3 * 256) * BPAD * 2;          // 147456
    const int fa_sm    = FA_SMEM_BYTES;                           // 174080
    cudaFuncSetAttribute(gemm_bf16<1, 128, 0>, cudaFuncAttributeMaxDynamicSharedMemorySize, gb128_sm);
    cudaFuncSetAttribute(gemm_bf16<0, 128, 0>, cudaFuncAttributeMaxDynamicSharedMemorySize, gb128_sm);
    cudaFuncSetAttribute(gemm_bf16<0, 256, 0>, cudaFuncAttributeMaxDynamicSharedMemorySize, gb256_sm);
    cudaFuncSetAttribute(gemm_bf16<1, 256, 0>, cudaFuncAttributeMaxDynamicSharedMemorySize, gb256_sm);
    cudaFuncSetAttribute(gemm_bf16<2, 256, 1>, cudaFuncAttributeMaxDynamicSharedMemorySize, gb256_sm);
    cudaFuncSetAttribute(gemm_e1f, cudaFuncAttributeMaxDynamicSharedMemorySize, e1f_sm);
    cudaFuncSetAttribute(flash_attn_bf16, cudaFuncAttributeMaxDynamicSharedMemorySize, fa_sm);

    transpose_all<<<497, dim3(32, 8)>>>(We1, wb_e1, We2, wb_e2, Wq, wb_q,
                                        Wk, Wv, wb_kv, Wd1, wb_d1, Wd2, wb_d2,
                                        bk, bv, bias_kv);

    const int M = RTOT;
    // encode stage 1: both inputs in one launch (grid 512)
    gemm_e1f<<<dim3(1, 2 * M / 128), 256, e1f_sm>>>(mainf, feat, wb_e1, be1, p_mid2, M, MID, HH);
    // encode stage 2, both halves in one launch (M = 65536)
    gemm_bf16<1, 128, 0><<<dim3(1, 2 * M / 128), 256, gb128_sm>>>(p_mid2, wb_e2, be2, p_mf, 2 * M, LAT, MID);
    // q (from m) and fused k+v (from f)
    gemm_bf16<0, 128, 0><<<dim3(1, M / 128), 256, gb128_sm>>>(p_mf, wb_q, bq, p_q, M, LAT, LAT);
    gemm_bf16<0, 256, 0><<<dim3(1, M / 128), 256, gb256_sm>>>(p_mf + (long)M * LAT, wb_kv, bias_kv, p_kv, M, 256, LAT);
    // attention
    flash_attn_bf16<<<dim3(N1 / FA_BM, BB), 256, fa_sm>>>(p_q, p_kv, p_attn);
    // decode
    gemm_bf16<1, 256, 0><<<dim3(1, M / 128), 256, gb256_sm>>>(p_attn, wb_d1, bd1, p_mid2, M, MID, LAT);
    gemm_bf16<2, 256, 1><<<dim3(3, M / 128), 256, gb256_sm>>>(p_mid2, wb_d2, bd2, out, M, HH, MID);
}